// round 4
// baseline (speedup 1.0000x reference)
#include <cuda_runtime.h>

#define BB 4
#define NN 1024
#define INF 256
#define OUTF 256
#define NH 8
#define BN (BB*NN)

// ---------------- scratch (allocation-free) ----------------
__device__ float g_buf[BN*OUTF];   // g = h @ W  (4 MB)
__device__ float ELraw[BN*NH];
__device__ float ERraw[BN*NH];
__device__ float Lbuf[BN*16];      // [exp(el) x8, exp(.2el) x8]
__device__ float Rbuf[BN*16];      // [exp(er) x8, exp(.2er) x8]
__device__ float c_buf[BN*NH];     // 1/s[b,j,h]

typedef unsigned long long u64;

__device__ __forceinline__ void ffma2(u64& d, u64 a, u64 b) {
    asm("fma.rn.f32x2 %0, %1, %2, %0;" : "+l"(d) : "l"(a), "l"(b));
}
__device__ __forceinline__ u64 fadd2(u64 a, u64 b) {
    u64 r; asm("add.rn.f32x2 %0, %1, %2;" : "=l"(r) : "l"(a), "l"(b)); return r;
}
union U2 { u64 u; float2 f; };

// ---------------------------------------------------------------------------
// K1: g = X @ W, 64x64 tile, 4x4 micro-tile, f32x2, fused el/er epilogue.
// ---------------------------------------------------------------------------
__global__ __launch_bounds__(256) void k_gemm(const float* __restrict__ X,
                                              const float* __restrict__ W,
                                              const float* __restrict__ aw) {
    __shared__ __align__(16) float2 Xs2[16][64];
    __shared__ __align__(16) float  Ws [16][64];
    const int t = threadIdx.x;
    const int row0 = (blockIdx.x >> 2) * 64;
    const int cb   = (blockIdx.x & 3) * 64;
    const int tx = t & 15, ty = t >> 4;
    const int r0 = ty * 4, c0 = tx * 4;

    u64 acc[4][2];
#pragma unroll
    for (int r = 0; r < 4; r++) { acc[r][0] = 0ull; acc[r][1] = 0ull; }

    const int lr = t >> 2, lk4 = (t & 3) * 4;
    const int wk = t >> 4, wc = (t & 15) * 4;

    for (int k0 = 0; k0 < INF; k0 += 16) {
        float4 xv = *reinterpret_cast<const float4*>(&X[(row0 + lr) * INF + k0 + lk4]);
        float4 wv = *reinterpret_cast<const float4*>(&W[(k0 + wk) * OUTF + cb + wc]);
        __syncthreads();
        Xs2[lk4 + 0][lr] = make_float2(xv.x, xv.x);
        Xs2[lk4 + 1][lr] = make_float2(xv.y, xv.y);
        Xs2[lk4 + 2][lr] = make_float2(xv.z, xv.z);
        Xs2[lk4 + 3][lr] = make_float2(xv.w, xv.w);
        *reinterpret_cast<float4*>(&Ws[wk][wc]) = wv;
        __syncthreads();
#pragma unroll
        for (int kk = 0; kk < 16; kk++) {
            const ulonglong2* xp = reinterpret_cast<const ulonglong2*>(&Xs2[kk][r0]);
            ulonglong2 xa = xp[0], xb = xp[1];
            ulonglong2 wv2 = *reinterpret_cast<const ulonglong2*>(&Ws[kk][c0]);
            ffma2(acc[0][0], xa.x, wv2.x); ffma2(acc[0][1], xa.x, wv2.y);
            ffma2(acc[1][0], xa.y, wv2.x); ffma2(acc[1][1], xa.y, wv2.y);
            ffma2(acc[2][0], xb.x, wv2.x); ffma2(acc[2][1], xb.x, wv2.y);
            ffma2(acc[3][0], xb.y, wv2.x); ffma2(acc[3][1], xb.y, wv2.y);
        }
    }

    const float4* awp = reinterpret_cast<const float4*>(aw);
    float4 aL = awp[tx & 7];
    float4 aR = awp[8 + (tx & 7)];

#pragma unroll
    for (int r = 0; r < 4; r++) {
        U2 a, b; a.u = acc[r][0]; b.u = acc[r][1];
        float4 o = make_float4(a.f.x, a.f.y, b.f.x, b.f.y);
        *reinterpret_cast<float4*>(&g_buf[(row0 + r0 + r) * OUTF + cb + c0]) = o;

        float el = o.x*aL.x + o.y*aL.y + o.z*aL.z + o.w*aL.w;
        float er = o.x*aR.x + o.y*aR.y + o.z*aR.z + o.w*aR.w;
        el += __shfl_xor_sync(0xffffffffu, el, 1);
        el += __shfl_xor_sync(0xffffffffu, el, 2);
        el += __shfl_xor_sync(0xffffffffu, el, 4);
        er += __shfl_xor_sync(0xffffffffu, er, 1);
        er += __shfl_xor_sync(0xffffffffu, er, 2);
        er += __shfl_xor_sync(0xffffffffu, er, 4);
        if ((tx & 7) == 0) {
            int head = (cb >> 5) + (tx >> 3);
            int row = row0 + r0 + r;
            ELraw[row * NH + head] = el;
            ERraw[row * NH + head] = er;
        }
    }
}

// ---------------------------------------------------------------------------
__global__ __launch_bounds__(256) void k_exp() {
    int idx = blockIdx.x * 256 + threadIdx.x;
    int row = idx >> 3, h = idx & 7;
    float el = ELraw[idx], er = ERraw[idx];
    Lbuf[row * 16 + h]     = __expf(el);
    Lbuf[row * 16 + 8 + h] = __expf(0.2f * el);
    Rbuf[row * 16 + h]     = __expf(er);
    Rbuf[row * 16 + 8 + h] = __expf(0.2f * er);
}

// ---------------------------------------------------------------------------
// K2: c[b,j,h] = 1 / sum_i adj[b,i,j]*wexp(i,j,h)
// ---------------------------------------------------------------------------
__global__ __launch_bounds__(256) void k_c(const float* __restrict__ adj) {
    __shared__ float ssum[8][32][8];
    const int t = threadIdx.x;
    const int b = blockIdx.x >> 5;
    const int j0 = (blockIdx.x & 31) * 32;
    const int jl = t & 31, ig = t >> 5;

    const float4* rrow = reinterpret_cast<const float4*>(&Rbuf[(b * NN + j0 + jl) * 16]);
    float4 rp0 = rrow[0], rp1 = rrow[1], rn0 = rrow[2], rn1 = rrow[3];
    float EPr[8] = {rp0.x, rp0.y, rp0.z, rp0.w, rp1.x, rp1.y, rp1.z, rp1.w};
    float ENr[8] = {rn0.x, rn0.y, rn0.z, rn0.w, rn1.x, rn1.y, rn1.z, rn1.w};

    float acc[8];
#pragma unroll
    for (int h = 0; h < 8; h++) acc[h] = 0.f;

    const float* adjcol = adj + (size_t)b * NN * NN + j0 + jl;
    for (int i = ig; i < NN; i += 8) {
        float a = __ldg(adjcol + (size_t)i * NN);
        const float4* lr = reinterpret_cast<const float4*>(&Lbuf[(b * NN + i) * 16]);
        float4 lp0 = __ldg(&lr[0]), lp1 = __ldg(&lr[1]);
        float4 ln0 = __ldg(&lr[2]), ln1 = __ldg(&lr[3]);
        float EPl[8] = {lp0.x, lp0.y, lp0.z, lp0.w, lp1.x, lp1.y, lp1.z, lp1.w};
        float ENl[8] = {ln0.x, ln0.y, ln0.z, ln0.w, ln1.x, ln1.y, ln1.z, ln1.w};
#pragma unroll
        for (int h = 0; h < 8; h++) {
            float p = EPl[h] * EPr[h];
            float q = ENl[h] * ENr[h];
            float w = (p >= 1.0f) ? p : q;
            acc[h] = fmaf(a, w, acc[h]);
        }
    }
#pragma unroll
    for (int h = 0; h < 8; h++) ssum[ig][jl][h] = acc[h];
    __syncthreads();

    {
        int jl2 = t >> 3, h = t & 7;
        float s = 0.f;
#pragma unroll
        for (int g = 0; g < 8; g++) s += ssum[g][jl2][h];
        c_buf[(b * NN + j0 + jl2) * NH + h] = 1.0f / s;
    }
}

// ---------------------------------------------------------------------------
// K3: out[b,i,h,:] = sum_j adj*wexp*c[j,h] * g[b,j,h,:]
// Grid 128 = (b, 32-row i tile). 512 threads, warp = (head, j-half).
// j chunk = 64; warp sweeps its 32-j half with 4 il x 8 d register tile.
// Weights stored duplicated {w,w} -> sweep = 4 LDS.128 + 16 FFMA2 per jj.
// Halves combined via smem at the end.
// ---------------------------------------------------------------------------
struct SmemAgg {
    float4 Gs4[64][64];      // g tile [jj][h*8 + d4]             64 KB
    float2 Wgt[8][64][32];   // dup weights [h][jj][il]          128 KB
    float  adj_s[32][65];    // padded                           8.3 KB
    float  Ltile[32][16];                                      // 2 KB
    float4 Rv[64][8];        // (Rp*c, Rn*c, c, 0)                8 KB
};

__global__ __launch_bounds__(512) void k_agg(const float* __restrict__ adj,
                                             float* __restrict__ out) {
    extern __shared__ char smraw[];
    SmemAgg& sm = *reinterpret_cast<SmemAgg*>(smraw);
    const int t = threadIdx.x;
    const int b = blockIdx.x >> 5;
    const int i0 = (blockIdx.x & 31) * 32;

    {   // stage Ltile (512 entries, one per thread)
        int il = t >> 4, c = t & 15;
        sm.Ltile[il][c] = Lbuf[(b * NN + i0 + il) * 16 + c];
    }
    __syncthreads();

    const int h    = (t >> 5) & 7;   // head (both phases)
    const int half = t >> 8;         // j-half of the 64-chunk
    const int q    = (t >> 3) & 3;   // d-group
    const int ig   = t & 7;          // il-group
    const int wil  = t & 31;         // weight-phase lane = il
    const int jbase = half * 32;
    const float Lp = sm.Ltile[wil][h];
    const float Ln = sm.Ltile[wil][8 + h];

    u64 acc2[4][4];
#pragma unroll
    for (int r = 0; r < 4; r++)
#pragma unroll
        for (int c = 0; c < 4; c++) acc2[r][c] = 0ull;

    const float4* g4 = reinterpret_cast<const float4*>(g_buf);

    for (int j0 = 0; j0 < NN; j0 += 64) {
        __syncthreads();

        // stage adj tile (32 x 64)
#pragma unroll
        for (int m = 0; m < 4; m++) {
            int idx = t + m * 512;
            int il = idx >> 6, jj = idx & 63;
            sm.adj_s[il][jj] = adj[(size_t)(b * NN + i0 + il) * NN + j0 + jj];
        }
        // stage g tile (64 x 256 floats)
#pragma unroll
        for (int m = 0; m < 8; m++) {
            int v = t + m * 512;
            int jj = v >> 6, c4 = v & 63;
            sm.Gs4[jj][c4] = g4[(size_t)(b * NN + j0 + jj) * 64 + c4];
        }
        // stage per-(jj,h) scalars (512 entries)
        {
            int jj = t >> 3, rh = t & 7;
            float cc = c_buf[(b * NN + j0 + jj) * NH + rh];
            float Rp = Rbuf[(b * NN + j0 + jj) * 16 + rh] * cc;
            float Rn = Rbuf[(b * NN + j0 + jj) * 16 + 8 + rh] * cc;
            sm.Rv[jj][rh] = make_float4(Rp, Rn, cc, 0.f);
        }
        __syncthreads();

        // weight tile: warp (h,half) fills its jj half; lane = il
#pragma unroll 4
        for (int jj2 = 0; jj2 < 32; jj2++) {
            int jj = jbase + jj2;
            float4 rv = sm.Rv[jj][h];                 // broadcast
            float p  = Lp * rv.x;
            float qn = Ln * rv.y;
            float w  = (p >= rv.z) ? p : qn;          // Lp*Rp >= 1 <=> p >= c
            float a  = sm.adj_s[wil][jj] * w;
            sm.Wgt[h][jj][wil] = make_float2(a, a);
        }
        __syncthreads();

        // FMA sweep: 4 il x 8 d, 4 LDS.128 + 16 FFMA2 per jj
#pragma unroll 4
        for (int jj2 = 0; jj2 < 32; jj2++) {
            int jj = jbase + jj2;
            const ulonglong2* gp =
                reinterpret_cast<const ulonglong2*>(&sm.Gs4[jj][h * 8 + 2 * q]);
            ulonglong2 ga = gp[0], gb = gp[1];
            const ulonglong2* wp =
                reinterpret_cast<const ulonglong2*>(&sm.Wgt[h][jj][4 * ig]);
            ulonglong2 wa = wp[0], wb = wp[1];   // {w0,w0},{w1,w1},{w2,w2},{w3,w3}
            ffma2(acc2[0][0], wa.x, ga.x); ffma2(acc2[0][1], wa.x, ga.y);
            ffma2(acc2[0][2], wa.x, gb.x); ffma2(acc2[0][3], wa.x, gb.y);
            ffma2(acc2[1][0], wa.y, ga.x); ffma2(acc2[1][1], wa.y, ga.y);
            ffma2(acc2[1][2], wa.y, gb.x); ffma2(acc2[1][3], wa.y, gb.y);
            ffma2(acc2[2][0], wb.x, ga.x); ffma2(acc2[2][1], wb.x, ga.y);
            ffma2(acc2[2][2], wb.x, gb.x); ffma2(acc2[2][3], wb.x, gb.y);
            ffma2(acc2[3][0], wb.y, ga.x); ffma2(acc2[3][1], wb.y, ga.y);
            ffma2(acc2[3][2], wb.y, gb.x); ffma2(acc2[3][3], wb.y, gb.y);
        }
    }

    // combine halves: half1 dumps accs to smem (overlay on Gs4), half0 adds+stores
    __syncthreads();
    u64* red = reinterpret_cast<u64*>(&sm.Gs4[0][0]);
    if (half == 1) {
#pragma unroll
        for (int r = 0; r < 4; r++)
#pragma unroll
            for (int c = 0; c < 4; c++) red[(t - 256) * 16 + r * 4 + c] = acc2[r][c];
    }
    __syncthreads();
    if (half == 0) {
        float4* out4 = reinterpret_cast<float4*>(out);
#pragma unroll
        for (int il = 0; il < 4; il++) {
            u64 s0 = fadd2(acc2[il][0], red[t * 16 + il * 4 + 0]);
            u64 s1 = fadd2(acc2[il][1], red[t * 16 + il * 4 + 1]);
            u64 s2 = fadd2(acc2[il][2], red[t * 16 + il * 4 + 2]);
            u64 s3 = fadd2(acc2[il][3], red[t * 16 + il * 4 + 3]);
            U2 a0, a1, a2, a3; a0.u = s0; a1.u = s1; a2.u = s2; a3.u = s3;
            int i = i0 + 4 * ig + il;
            size_t base = (size_t)(b * NN + i) * 64 + h * 8 + 2 * q;
            out4[base]     = make_float4(a0.f.x, a0.f.y, a1.f.x, a1.f.y);
            out4[base + 1] = make_float4(a2.f.x, a2.f.y, a3.f.x, a3.f.y);
        }
    }
}

// ---------------------------------------------------------------------------
extern "C" void kernel_launch(void* const* d_in, const int* in_sizes, int n_in,
                              void* d_out, int out_size) {
    const float* h_in = (const float*)d_in[0];
    const float* adj  = (const float*)d_in[1];
    const float* W    = (const float*)d_in[2];
    const float* aw   = (const float*)d_in[3];
    float* out = (float*)d_out;

    static bool attr_set = false;
    if (!attr_set) {
        cudaFuncSetAttribute(k_agg, cudaFuncAttributeMaxDynamicSharedMemorySize,
                             (int)sizeof(SmemAgg));
        attr_set = true;
    }

    k_gemm<<<256, 256>>>(h_in, W, aw);
    k_exp<<<BN * NH / 256, 256>>>();
    k_c<<<(BB * NN) / 32, 256>>>(adj);
    k_agg<<<128, 512, sizeof(SmemAgg)>>>(adj, out);
}

// round 5
// speedup vs baseline: 1.4076x; 1.4076x over previous
#include <cuda_runtime.h>

#define BB 4
#define NN 1024
#define INF 256
#define OUTF 256
#define NH 8
#define BN (BB*NN)

// ---------------- scratch (allocation-free) ----------------
__device__ float g_buf[BN*OUTF];   // g = h @ W  (4 MB)
__device__ float ELraw[BN*NH];
__device__ float ERraw[BN*NH];
__device__ float Lbuf[BN*16];      // [exp(el) x8, exp(.2el) x8]
__device__ float Rbuf[BN*16];      // [exp(er) x8, exp(.2er) x8]
__device__ float c_buf[BN*NH];     // 1/s[b,j,h]

typedef unsigned long long u64;

__device__ __forceinline__ u64 pack2(float v) {
    u64 r; asm("mov.b64 %0, {%1, %1};" : "=l"(r) : "f"(v)); return r;
}
__device__ __forceinline__ void ffma2(u64& d, u64 a, u64 b) {
    asm("fma.rn.f32x2 %0, %1, %2, %0;" : "+l"(d) : "l"(a), "l"(b));
}
__device__ __forceinline__ u64 fadd2(u64 a, u64 b) {
    u64 r; asm("add.rn.f32x2 %0, %1, %2;" : "=l"(r) : "l"(a), "l"(b)); return r;
}
union U2 { u64 u; float2 f; };

// ---------------------------------------------------------------------------
// K1: g = X @ W, 64x64 tile, 4x4 micro-tile, f32x2, fused el/er epilogue.
// ---------------------------------------------------------------------------
__global__ __launch_bounds__(256) void k_gemm(const float* __restrict__ X,
                                              const float* __restrict__ W,
                                              const float* __restrict__ aw) {
    __shared__ __align__(16) float2 Xs2[16][64];
    __shared__ __align__(16) float  Ws [16][64];
    const int t = threadIdx.x;
    const int row0 = (blockIdx.x >> 2) * 64;
    const int cb   = (blockIdx.x & 3) * 64;
    const int tx = t & 15, ty = t >> 4;
    const int r0 = ty * 4, c0 = tx * 4;

    u64 acc[4][2];
#pragma unroll
    for (int r = 0; r < 4; r++) { acc[r][0] = 0ull; acc[r][1] = 0ull; }

    const int lr = t >> 2, lk4 = (t & 3) * 4;
    const int wk = t >> 4, wc = (t & 15) * 4;

    for (int k0 = 0; k0 < INF; k0 += 16) {
        float4 xv = *reinterpret_cast<const float4*>(&X[(row0 + lr) * INF + k0 + lk4]);
        float4 wv = *reinterpret_cast<const float4*>(&W[(k0 + wk) * OUTF + cb + wc]);
        __syncthreads();
        Xs2[lk4 + 0][lr] = make_float2(xv.x, xv.x);
        Xs2[lk4 + 1][lr] = make_float2(xv.y, xv.y);
        Xs2[lk4 + 2][lr] = make_float2(xv.z, xv.z);
        Xs2[lk4 + 3][lr] = make_float2(xv.w, xv.w);
        *reinterpret_cast<float4*>(&Ws[wk][wc]) = wv;
        __syncthreads();
#pragma unroll
        for (int kk = 0; kk < 16; kk++) {
            const ulonglong2* xp = reinterpret_cast<const ulonglong2*>(&Xs2[kk][r0]);
            ulonglong2 xa = xp[0], xb = xp[1];
            ulonglong2 wv2 = *reinterpret_cast<const ulonglong2*>(&Ws[kk][c0]);
            ffma2(acc[0][0], xa.x, wv2.x); ffma2(acc[0][1], xa.x, wv2.y);
            ffma2(acc[1][0], xa.y, wv2.x); ffma2(acc[1][1], xa.y, wv2.y);
            ffma2(acc[2][0], xb.x, wv2.x); ffma2(acc[2][1], xb.x, wv2.y);
            ffma2(acc[3][0], xb.y, wv2.x); ffma2(acc[3][1], xb.y, wv2.y);
        }
    }

    const float4* awp = reinterpret_cast<const float4*>(aw);
    float4 aL = awp[tx & 7];
    float4 aR = awp[8 + (tx & 7)];

#pragma unroll
    for (int r = 0; r < 4; r++) {
        U2 a, b; a.u = acc[r][0]; b.u = acc[r][1];
        float4 o = make_float4(a.f.x, a.f.y, b.f.x, b.f.y);
        *reinterpret_cast<float4*>(&g_buf[(row0 + r0 + r) * OUTF + cb + c0]) = o;

        float el = o.x*aL.x + o.y*aL.y + o.z*aL.z + o.w*aL.w;
        float er = o.x*aR.x + o.y*aR.y + o.z*aR.z + o.w*aR.w;
        el += __shfl_xor_sync(0xffffffffu, el, 1);
        el += __shfl_xor_sync(0xffffffffu, el, 2);
        el += __shfl_xor_sync(0xffffffffu, el, 4);
        er += __shfl_xor_sync(0xffffffffu, er, 1);
        er += __shfl_xor_sync(0xffffffffu, er, 2);
        er += __shfl_xor_sync(0xffffffffu, er, 4);
        if ((tx & 7) == 0) {
            int head = (cb >> 5) + (tx >> 3);
            int row = row0 + r0 + r;
            ELraw[row * NH + head] = el;
            ERraw[row * NH + head] = er;
        }
    }
}

// ---------------------------------------------------------------------------
__global__ __launch_bounds__(256) void k_exp() {
    int idx = blockIdx.x * 256 + threadIdx.x;
    int row = idx >> 3, h = idx & 7;
    float el = ELraw[idx], er = ERraw[idx];
    Lbuf[row * 16 + h]     = __expf(el);
    Lbuf[row * 16 + 8 + h] = __expf(0.2f * el);
    Rbuf[row * 16 + h]     = __expf(er);
    Rbuf[row * 16 + 8 + h] = __expf(0.2f * er);
}

// ---------------------------------------------------------------------------
// K2: c[b,j,h] = 1 / sum_i adj[b,i,j]*wexp(i,j,h).  512 threads.
// ---------------------------------------------------------------------------
__global__ __launch_bounds__(512) void k_c(const float* __restrict__ adj) {
    __shared__ float ssum[16][32][8];
    const int t = threadIdx.x;
    const int b = blockIdx.x >> 5;
    const int j0 = (blockIdx.x & 31) * 32;
    const int jl = t & 31, ig = t >> 5;

    const float4* rrow = reinterpret_cast<const float4*>(&Rbuf[(b * NN + j0 + jl) * 16]);
    float4 rp0 = rrow[0], rp1 = rrow[1], rn0 = rrow[2], rn1 = rrow[3];
    float EPr[8] = {rp0.x, rp0.y, rp0.z, rp0.w, rp1.x, rp1.y, rp1.z, rp1.w};
    float ENr[8] = {rn0.x, rn0.y, rn0.z, rn0.w, rn1.x, rn1.y, rn1.z, rn1.w};

    float acc[8];
#pragma unroll
    for (int h = 0; h < 8; h++) acc[h] = 0.f;

    const float* adjcol = adj + (size_t)b * NN * NN + j0 + jl;
    for (int i = ig; i < NN; i += 16) {
        float a = __ldg(adjcol + (size_t)i * NN);
        const float4* lr = reinterpret_cast<const float4*>(&Lbuf[(b * NN + i) * 16]);
        float4 lp0 = __ldg(&lr[0]), lp1 = __ldg(&lr[1]);
        float4 ln0 = __ldg(&lr[2]), ln1 = __ldg(&lr[3]);
        float EPl[8] = {lp0.x, lp0.y, lp0.z, lp0.w, lp1.x, lp1.y, lp1.z, lp1.w};
        float ENl[8] = {ln0.x, ln0.y, ln0.z, ln0.w, ln1.x, ln1.y, ln1.z, ln1.w};
#pragma unroll
        for (int h = 0; h < 8; h++) {
            float p = EPl[h] * EPr[h];
            float q = ENl[h] * ENr[h];
            float w = (p >= 1.0f) ? p : q;
            acc[h] = fmaf(a, w, acc[h]);
        }
    }
#pragma unroll
    for (int h = 0; h < 8; h++) ssum[ig][jl][h] = acc[h];
    __syncthreads();

    if (t < 256) {
        int jl2 = t >> 3, h = t & 7;
        float s = 0.f;
#pragma unroll
        for (int g = 0; g < 16; g++) s += ssum[g][jl2][h];
        c_buf[(b * NN + j0 + jl2) * NH + h] = 1.0f / s;
    }
}

// ---------------------------------------------------------------------------
// K3: out[b,i,h,:] = sum_j adj*wexp*c[j,h] * g[b,j,h,:]
// Grid 128 = (b, 32-row i tile). 512 thr = 16 warps = 8 heads x 2 j-halves.
// Chunk 64 j. Lane parity splits jj within a half. Thread tile: 8 il x 8 d,
// accs paired along d. Per jj: 4 LDS.128 (64 B) -> 64 FMA (1.0 B/FMA).
// Smem rows padded so parity lanes hit disjoint banks.
// ---------------------------------------------------------------------------
struct SmemAgg {
    float4 Gs4[64][65];      // g tile [jj][h*8+d4], padded row    66.6 KB
    float  Wgt[8][64][36];   // [h][jj][il], padded row            73.7 KB
    float  adj_s[32][65];    //                                     8.3 KB
    float  Ltile[32][16];    //                                     2 KB
    float4 Rv[64][8];        // (Rp*c, Rn*c, c, 0)                  8 KB
};

__global__ __launch_bounds__(512) void k_agg(const float* __restrict__ adj,
                                             float* __restrict__ out) {
    extern __shared__ char smraw[];
    SmemAgg& sm = *reinterpret_cast<SmemAgg*>(smraw);
    const int t = threadIdx.x;
    const int b = blockIdx.x >> 5;
    const int i0 = (blockIdx.x & 31) * 32;

    {   // stage Ltile
        int il = t >> 4, c = t & 15;
        sm.Ltile[il][c] = Lbuf[(b * NN + i0 + il) * 16 + c];
    }
    __syncthreads();

    const int l    = t & 31;
    const int h    = (t >> 5) & 7;     // head
    const int half = t >> 8;           // j-half of the 64-chunk
    const int jbase = half * 32;
    const int par  = l & 1;            // jj parity within half
    const int ilg  = (l >> 1) & 3;     // il group: il = 8*ilg..+7
    const int q    = l >> 3;           // d group: d = 8q..+7
    const float Lp = sm.Ltile[l][h];   // weight-phase values (lane = il)
    const float Ln = sm.Ltile[l][8 + h];

    u64 acc[8][4];
#pragma unroll
    for (int r = 0; r < 8; r++)
#pragma unroll
        for (int c = 0; c < 4; c++) acc[r][c] = 0ull;

    const float4* g4 = reinterpret_cast<const float4*>(g_buf);

    for (int j0 = 0; j0 < NN; j0 += 64) {
        __syncthreads();

        // stage adj tile (32 x 64)
#pragma unroll
        for (int m = 0; m < 4; m++) {
            int idx = t + m * 512;
            int il = idx >> 6, jj = idx & 63;
            sm.adj_s[il][jj] = adj[(size_t)(b * NN + i0 + il) * NN + j0 + jj];
        }
        // stage g tile (64 x 256 floats)
#pragma unroll
        for (int m = 0; m < 8; m++) {
            int v = t + m * 512;
            int jj = v >> 6, c4 = v & 63;
            sm.Gs4[jj][c4] = g4[(size_t)(b * NN + j0 + jj) * 64 + c4];
        }
        // stage per-(jj,h) scalars
        {
            int jj = t >> 3, rh = t & 7;
            float cc = c_buf[(b * NN + j0 + jj) * NH + rh];
            float Rp = Rbuf[(b * NN + j0 + jj) * 16 + rh] * cc;
            float Rn = Rbuf[(b * NN + j0 + jj) * 16 + 8 + rh] * cc;
            sm.Rv[jj][rh] = make_float4(Rp, Rn, cc, 0.f);
        }
        __syncthreads();

        // weight tile: warp (h,half) fills its 32 jj; lane = il. Scalar store.
#pragma unroll 4
        for (int jj2 = 0; jj2 < 32; jj2++) {
            int jj = jbase + jj2;
            float4 rv = sm.Rv[jj][h];
            float p  = Lp * rv.x;
            float qn = Ln * rv.y;
            float w  = (p >= rv.z) ? p : qn;
            sm.Wgt[h][jj][l] = sm.adj_s[l][jj] * w;
        }
        __syncthreads();

        // FMA sweep: parity lane takes jj = jbase + 2*jj2 + par
#pragma unroll 4
        for (int jj2 = 0; jj2 < 16; jj2++) {
            int jj = jbase + 2 * jj2 + par;
            const ulonglong2* gp =
                reinterpret_cast<const ulonglong2*>(&sm.Gs4[jj][h * 8 + 2 * q]);
            ulonglong2 ga = gp[0], gb = gp[1];      // d pairs: 8q..8q+7
            const float4* wp =
                reinterpret_cast<const float4*>(&sm.Wgt[h][jj][8 * ilg]);
            float4 wv0 = wp[0], wv1 = wp[1];        // il 8ilg..8ilg+7
            u64 wd[8];
            wd[0] = pack2(wv0.x); wd[1] = pack2(wv0.y);
            wd[2] = pack2(wv0.z); wd[3] = pack2(wv0.w);
            wd[4] = pack2(wv1.x); wd[5] = pack2(wv1.y);
            wd[6] = pack2(wv1.z); wd[7] = pack2(wv1.w);
#pragma unroll
            for (int il = 0; il < 8; il++) {
                ffma2(acc[il][0], wd[il], ga.x);
                ffma2(acc[il][1], wd[il], ga.y);
                ffma2(acc[il][2], wd[il], gb.x);
                ffma2(acc[il][3], wd[il], gb.y);
            }
        }
    }

    // parity reduction: lane xor 1
#pragma unroll
    for (int r = 0; r < 8; r++)
#pragma unroll
        for (int c = 0; c < 4; c++) {
            u64 o = __shfl_xor_sync(0xffffffffu, acc[r][c], 1);
            acc[r][c] = fadd2(acc[r][c], o);
        }

    // combine halves via smem (overlay on Gs4); par0 lanes only
    __syncthreads();
    u64* red = reinterpret_cast<u64*>(&sm.Gs4[0][0]);
    const int slot = (h * 16 + (ilg * 4 + q)) * 32;   // 128 slots x 32 u64
    if (half == 1 && par == 0) {
#pragma unroll
        for (int r = 0; r < 8; r++)
#pragma unroll
            for (int c = 0; c < 4; c++) red[slot + r * 4 + c] = acc[r][c];
    }
    __syncthreads();
    if (half == 0 && par == 0) {
        float4* out4 = reinterpret_cast<float4*>(out);
#pragma unroll
        for (int il = 0; il < 8; il++) {
            u64 s0 = fadd2(acc[il][0], red[slot + il * 4 + 0]);
            u64 s1 = fadd2(acc[il][1], red[slot + il * 4 + 1]);
            u64 s2 = fadd2(acc[il][2], red[slot + il * 4 + 2]);
            u64 s3 = fadd2(acc[il][3], red[slot + il * 4 + 3]);
            U2 a0, a1, a2, a3; a0.u = s0; a1.u = s1; a2.u = s2; a3.u = s3;
            int i = i0 + 8 * ilg + il;
            size_t base = (size_t)(b * NN + i) * 64 + h * 8 + 2 * q;
            out4[base]     = make_float4(a0.f.x, a0.f.y, a1.f.x, a1.f.y);
            out4[base + 1] = make_float4(a2.f.x, a2.f.y, a3.f.x, a3.f.y);
        }
    }
}

// ---------------------------------------------------------------------------
extern "C" void kernel_launch(void* const* d_in, const int* in_sizes, int n_in,
                              void* d_out, int out_size) {
    const float* h_in = (const float*)d_in[0];
    const float* adj  = (const float*)d_in[1];
    const float* W    = (const float*)d_in[2];
    const float* aw   = (const float*)d_in[3];
    float* out = (float*)d_out;

    static bool attr_set = false;
    if (!attr_set) {
        cudaFuncSetAttribute(k_agg, cudaFuncAttributeMaxDynamicSharedMemorySize,
                             (int)sizeof(SmemAgg));
        attr_set = true;
    }

    k_gemm<<<256, 256>>>(h_in, W, aw);
    k_exp<<<BN * NH / 256, 256>>>();
    k_c<<<(BB * NN) / 32, 512>>>(adj);
    k_agg<<<128, 512, sizeof(SmemAgg)>>>(adj, out);
}